// round 4
// baseline (speedup 1.0000x reference)
#include <cuda_runtime.h>
#include <cstdint>

#define NB 512
#define NS 2048
#define NK 128
#define NE 64
#define NA 128
#define NH 4
#define NDK 32
#define NOD 64
#define NFOH 15
#define NFMH 4
#define NFSP 4
#define NLSP 50
#define NVOH 10001
#define NVMH 100001
#define NVSP 10001
#define ND0 1728

// ---------------- scratch (static device globals; no allocation) ----------------
__device__ uint32_t g_rowhash[NFMH * NVMH];
__device__ uint32_t g_th[NFMH * NB];
__device__ int      g_sel[NFMH * NB * NK];
__device__ float    g_feats[NB * ND0];
__device__ float    g_x1[NB * 1024];
__device__ float    g_x2[NB * 512];
__device__ float    g_x3[NB * 256];

__device__ __forceinline__ unsigned long long pack2(float x, float y) {
    return ((unsigned long long)__float_as_uint(y) << 32) | (unsigned long long)__float_as_uint(x);
}

// ---------------- K1: LSH signature per multi-hot table row ----------------
// warp handles 2 rows; lane j computes bit j for both rows via packed f32x2 FMA (exact fp32).
__global__ __launch_bounds__(256) void hash_rows_kernel(
    const float* __restrict__ tables, const float* __restrict__ hw, int nrows)
{
    __shared__ unsigned long long hwdup[64][32];   // (h,h) per (e, bit)
    __shared__ unsigned long long embbuf[8][64];   // (rowA[e], rowB[e]) per warp
    int tid = threadIdx.x;
    for (int i = tid; i < 64 * 32; i += 256) {
        float h = hw[i];
        hwdup[i >> 5][i & 31] = pack2(h, h);
    }
    __syncthreads();
    int w = tid >> 5, lane = tid & 31;
    int npairs = (nrows + 1) >> 1;
    for (int p = blockIdx.x * 8 + w; p < npairs; p += gridDim.x * 8) {
        int rA = 2 * p, rB = rA + 1;
        const float* Ap = tables + (size_t)rA * NE;
        const float* Bp = tables + (size_t)(rB < nrows ? rB : rA) * NE;
        embbuf[w][lane]      = pack2(Ap[lane],      Bp[lane]);
        embbuf[w][lane + 32] = pack2(Ap[lane + 32], Bp[lane + 32]);
        __syncwarp();
        unsigned long long acc = 0ull;  // (0.f, 0.f)
        #pragma unroll
        for (int e = 0; e < 64; e++) {
            unsigned long long v = embbuf[w][e];
            unsigned long long hh = hwdup[e][lane];
            asm("fma.rn.f32x2 %0, %1, %2, %0;" : "+l"(acc) : "l"(v), "l"(hh));
        }
        float ax = __uint_as_float((unsigned)acc);
        float ay = __uint_as_float((unsigned)(acc >> 32));
        unsigned mA = __ballot_sync(0xffffffffu, ax > 0.f);
        unsigned mB = __ballot_sync(0xffffffffu, ay > 0.f);
        if (lane == 0) {
            g_rowhash[rA] = mA;
            if (rB < nrows) g_rowhash[rB] = mB;
        }
        __syncwarp();
    }
}

// ---------------- one-hot gather into feats ----------------
__global__ void oh_kernel(const float* __restrict__ tables, const int* __restrict__ ids)
{
    int b = blockIdx.x, t = threadIdx.x;           // 960 threads
    int f = t >> 6, e = t & 63;
    int id = ids[b * NFOH + f];
    g_feats[b * ND0 + f * 64 + e] = tables[((size_t)f * NVOH + id) * NE + e];
}

// ---------------- special sum-combiner gather ----------------
__global__ void sp_kernel(const float* __restrict__ tables, const int* __restrict__ ids)
{
    int b = blockIdx.x, t = threadIdx.x;           // 256 threads
    int f = t >> 6, e = t & 63;
    const int* idp = ids + ((size_t)f * NB + b) * NLSP;
    float acc = 0.f;
    for (int l = 0; l < NLSP; l++) {
        int id = idp[l];
        if (id >= 0) acc += tables[((size_t)f * NVSP + id) * NE + e];
    }
    g_feats[b * ND0 + NFOH * 64 + f * 64 + e] = acc;
}

// ---------------- target hashes (exact fp32, bit j == lane j like K1) ----------------
__global__ void th_kernel(const float* __restrict__ hw)
{
    __shared__ float hws[2048];
    for (int i = threadIdx.x; i < 2048; i += blockDim.x) hws[i] = hw[i];
    __syncthreads();
    int gw = (blockIdx.x * blockDim.x + threadIdx.x) >> 5;
    int lane = threadIdx.x & 31;
    if (gw >= NFMH * NB) return;
    int f = gw >> 9, b = gw & 511;
    const float* tgt = g_feats + b * ND0 + f * 64;
    float acc = 0.f;
    #pragma unroll
    for (int e = 0; e < 64; e++) acc = fmaf(tgt[e], hws[e * 32 + lane], acc);
    unsigned m = __ballot_sync(0xffffffffu, acc > 0.f);
    if (lane == 0) g_th[f * NB + b] = m;
}

// ---------------- top-K by counting-select (jax lower-index-first tie-break) ----------------
__global__ __launch_bounds__(256) void topk_kernel(const int* __restrict__ mh_ids)
{
    int b = blockIdx.x, f = blockIdx.y, t = threadIdx.x;
    __shared__ unsigned char ds[NS];
    __shared__ int ids_s[NS];
    __shared__ int hist[40];
    __shared__ int scanbuf[8];
    __shared__ int sh_dstar, sh_quota, sh_cnt;
    if (t < 40) hist[t] = 0;
    if (t == 0) sh_cnt = 0;
    __syncthreads();
    unsigned th = g_th[f * NB + b];
    const int* idp = mh_ids + ((size_t)f * NB + b) * NS;
    const uint32_t* rh = g_rowhash + (size_t)f * NVMH;
    int base = t * 8;
    #pragma unroll
    for (int i = 0; i < 8; i++) {
        int s = base + i;
        int id = idp[s];
        int d = (id >= 0) ? __popc(rh[id] ^ th) : 33;
        ds[s] = (unsigned char)d;
        ids_s[s] = id;
        atomicAdd(&hist[d], 1);
    }
    __syncthreads();
    if (t == 0) {
        int cum = 0, dstar = 33, less = 0;
        for (int d = 0; d <= 33; d++) {
            if (cum + hist[d] >= NK) { dstar = d; less = cum; break; }
            cum += hist[d];
        }
        sh_dstar = dstar; sh_quota = NK - less;
    }
    __syncthreads();
    int dstar = sh_dstar, quota = sh_quota;
    int myTie = 0;
    #pragma unroll
    for (int i = 0; i < 8; i++) myTie += (ds[base + i] == dstar) ? 1 : 0;
    // exclusive scan over threads (index order preserved within thread chunks)
    int lane = t & 31, wid = t >> 5;
    int inc = myTie;
    #pragma unroll
    for (int o = 1; o < 32; o <<= 1) {
        int n = __shfl_up_sync(0xffffffffu, inc, o);
        if (lane >= o) inc += n;
    }
    if (lane == 31) scanbuf[wid] = inc;
    __syncthreads();
    if (t == 0) {
        int run = 0;
        for (int wI = 0; wI < 8; wI++) { int v = scanbuf[wI]; scanbuf[wI] = run; run += v; }
    }
    __syncthreads();
    int tiebase = scanbuf[wid] + inc - myTie;
    int* outp = g_sel + ((size_t)f * NB + b) * NK;
    int tr = 0;
    #pragma unroll
    for (int i = 0; i < 8; i++) {
        int s = base + i; int d = ds[s];
        bool sel = false;
        if (d < dstar) sel = true;
        else if (d == dstar) { sel = (tiebase + tr) < quota; tr++; }
        if (sel) { int pos = atomicAdd(&sh_cnt, 1); outp[pos] = ids_s[s]; }
    }
}

// ---------------- 1-query attention, algebraically restructured (exact fp32) ----------------
// scores[h,s] = emb_s . wv[h] + cb[h]   with wv[h] = kW_h @ q_h   (22x fewer FLOPs)
// out[h*32+d] = c_h . vW[:,h*32+d] + vb  with c_h = sum_s a[h,s] emb_s
__global__ __launch_bounds__(128) void attn_kernel(
    const float* __restrict__ tables, const int* __restrict__ key_ids, int key_stride,
    const float* __restrict__ qW, const float* __restrict__ qb,
    const float* __restrict__ kW, const float* __restrict__ kb,
    const float* __restrict__ vW, const float* __restrict__ vb,
    const float* __restrict__ oW, const float* __restrict__ ob,
    int out_off)
{
    int b = blockIdx.x, f = blockIdx.y, t = threadIdx.x;
    __shared__ float bigbuf[8320];   // union: kW staged [64][129] / emb [128][65]
    __shared__ float tgt[64];
    __shared__ float q[128];
    __shared__ float wv[4][64];
    __shared__ float cbh[4];
    __shared__ float sc[4][128];
    __shared__ float ch[4][64];
    __shared__ float oatt[128];

    const float* qWf = qW + (size_t)f * 64 * 128;
    const float* kWf = kW + (size_t)f * 64 * 128;
    const float* vWf = vW + (size_t)f * 64 * 128;
    const float* oWf = oW + (size_t)f * 128 * 64;

    if (t < 64) tgt[t] = g_feats[b * ND0 + f * 64 + t];
    __syncthreads();

    // q projection
    {
        float acc = qb[f * 128 + t];
        #pragma unroll 8
        for (int e = 0; e < 64; e++) acc = fmaf(tgt[e], qWf[e * 128 + t], acc);
        q[t] = acc;
    }
    // stage kW into shared with pad-129 (conflict-free strided reads)
    {
        const float4* k4 = reinterpret_cast<const float4*>(kWf);
        #pragma unroll
        for (int j = 0; j < 16; j++) {
            int idx = t + 128 * j;              // float4 index
            float4 v = k4[idx];
            int e = idx >> 5;
            int c = (idx & 31) * 4;
            float* dst = &bigbuf[e * 129 + c];
            dst[0] = v.x; dst[1] = v.y; dst[2] = v.z; dst[3] = v.w;
        }
    }
    __syncthreads();
    // wv[h][e] = sum_d q[h*32+d] * kW[e][h*32+d] ; cb[h] = q_h . kb_h
    {
        int h0 = t >> 6, e = t & 63;
        for (int hh = h0; hh < 4; hh += 2) {
            float acc = 0.f;
            #pragma unroll 8
            for (int d = 0; d < 32; d++)
                acc = fmaf(q[hh * 32 + d], bigbuf[e * 129 + hh * 32 + d], acc);
            wv[hh][e] = acc;
        }
        if (t < 4) {
            float acc = 0.f;
            #pragma unroll
            for (int d = 0; d < 32; d++) acc = fmaf(q[t * 32 + d], kb[f * 128 + t * 32 + d], acc);
            cbh[t] = acc;
        }
    }
    __syncthreads();
    // gather 128 key embeddings into shared (pad-65), overwrite kW stage
    {
        const int* myids = key_ids + ((size_t)f * NB + b) * key_stride;
        int e4 = (t & 15) * 4;
        int srow = t >> 4;
        #pragma unroll
        for (int j = 0; j < 16; j++) {
            int s = srow + 8 * j;
            int id = myids[s];
            if (id < 0) id = 0;
            const float* row = tables + ((size_t)f * NVMH + id) * NE;
            float4 v = *reinterpret_cast<const float4*>(row + e4);
            float* dst = &bigbuf[s * 65 + e4];
            dst[0] = v.x; dst[1] = v.y; dst[2] = v.z; dst[3] = v.w;
        }
    }
    __syncthreads();
    // scores
    {
        int s = t;
        float a0 = 0.f, a1 = 0.f, a2 = 0.f, a3 = 0.f;
        #pragma unroll 8
        for (int e = 0; e < 64; e++) {
            float v = bigbuf[s * 65 + e];
            a0 = fmaf(v, wv[0][e], a0);
            a1 = fmaf(v, wv[1][e], a1);
            a2 = fmaf(v, wv[2][e], a2);
            a3 = fmaf(v, wv[3][e], a3);
        }
        const float scale = 0.17677669529663688f; // 1/sqrt(32)
        sc[0][s] = (a0 + cbh[0]) * scale;
        sc[1][s] = (a1 + cbh[1]) * scale;
        sc[2][s] = (a2 + cbh[2]) * scale;
        sc[3][s] = (a3 + cbh[3]) * scale;
    }
    __syncthreads();
    // softmax: warp h handles head h over 128 keys
    {
        int h = t >> 5, lane = t & 31;
        float v0 = sc[h][lane], v1 = sc[h][lane + 32], v2 = sc[h][lane + 64], v3 = sc[h][lane + 96];
        float m = fmaxf(fmaxf(v0, v1), fmaxf(v2, v3));
        #pragma unroll
        for (int o = 16; o; o >>= 1) m = fmaxf(m, __shfl_xor_sync(0xffffffffu, m, o));
        float e0 = expf(v0 - m), e1 = expf(v1 - m), e2 = expf(v2 - m), e3 = expf(v3 - m);
        float s4 = e0 + e1 + e2 + e3;
        #pragma unroll
        for (int o = 16; o; o >>= 1) s4 += __shfl_xor_sync(0xffffffffu, s4, o);
        float inv = 1.f / s4;
        sc[h][lane] = e0 * inv; sc[h][lane + 32] = e1 * inv;
        sc[h][lane + 64] = e2 * inv; sc[h][lane + 96] = e3 * inv;
    }
    __syncthreads();
    // c_h[e] = sum_s a[h][s] * emb[s][e]
    {
        for (int idx = t; idx < 256; idx += 128) {
            int h = idx >> 6, e = idx & 63;
            float acc = 0.f;
            #pragma unroll 8
            for (int s = 0; s < 128; s++) acc = fmaf(sc[h][s], bigbuf[s * 65 + e], acc);
            ch[h][e] = acc;
        }
    }
    __syncthreads();
    // v projection of c
    {
        int h = t >> 5;
        float acc = vb[f * 128 + t];
        #pragma unroll 8
        for (int e = 0; e < 64; e++) acc = fmaf(ch[h][e], vWf[e * 128 + t], acc);
        oatt[t] = acc;
    }
    __syncthreads();
    // output projection
    if (t < 64) {
        float acc = ob[f * 64 + t];
        #pragma unroll 8
        for (int a = 0; a < 128; a++) acc = fmaf(oatt[a], oWf[a * 64 + t], acc);
        g_feats[b * ND0 + out_off + f * 64 + t] = acc;
    }
}

// ---------------- MLP GEMM: C = relu?(A@W + b), fp32, 64x64x16 tiles ----------------
template<bool RELU>
__global__ __launch_bounds__(256) void gemm_kernel(
    const float* __restrict__ Ag, const float* __restrict__ Wg,
    const float* __restrict__ bias, float* __restrict__ Cg,
    int M, int N, int Kd)
{
    __shared__ float As[16][64];
    __shared__ float Ws[16][64];
    int t = threadIdx.x;
    int m0 = blockIdx.y * 64, n0 = blockIdx.x * 64;
    int am = t >> 2, ak = (t & 3) * 4;
    int wk = t >> 4, wn = (t & 15) * 4;
    int tm = (t >> 4) * 4, tn = (t & 15) * 4;
    float acc[4][4] = {};
    for (int k0 = 0; k0 < Kd; k0 += 16) {
        float4 a4 = *reinterpret_cast<const float4*>(Ag + (size_t)(m0 + am) * Kd + k0 + ak);
        float4 w4 = *reinterpret_cast<const float4*>(Wg + (size_t)(k0 + wk) * N + n0 + wn);
        __syncthreads();
        As[ak][am] = a4.x; As[ak + 1][am] = a4.y; As[ak + 2][am] = a4.z; As[ak + 3][am] = a4.w;
        *reinterpret_cast<float4*>(&Ws[wk][wn]) = w4;
        __syncthreads();
        #pragma unroll
        for (int k = 0; k < 16; k++) {
            float4 av = *reinterpret_cast<const float4*>(&As[k][tm]);
            float4 wv = *reinterpret_cast<const float4*>(&Ws[k][tn]);
            acc[0][0] = fmaf(av.x, wv.x, acc[0][0]); acc[0][1] = fmaf(av.x, wv.y, acc[0][1]);
            acc[0][2] = fmaf(av.x, wv.z, acc[0][2]); acc[0][3] = fmaf(av.x, wv.w, acc[0][3]);
            acc[1][0] = fmaf(av.y, wv.x, acc[1][0]); acc[1][1] = fmaf(av.y, wv.y, acc[1][1]);
            acc[1][2] = fmaf(av.y, wv.z, acc[1][2]); acc[1][3] = fmaf(av.y, wv.w, acc[1][3]);
            acc[2][0] = fmaf(av.z, wv.x, acc[2][0]); acc[2][1] = fmaf(av.z, wv.y, acc[2][1]);
            acc[2][2] = fmaf(av.z, wv.z, acc[2][2]); acc[2][3] = fmaf(av.z, wv.w, acc[2][3]);
            acc[3][0] = fmaf(av.w, wv.x, acc[3][0]); acc[3][1] = fmaf(av.w, wv.y, acc[3][1]);
            acc[3][2] = fmaf(av.w, wv.z, acc[3][2]); acc[3][3] = fmaf(av.w, wv.w, acc[3][3]);
        }
    }
    float4 b4 = *reinterpret_cast<const float4*>(bias + n0 + tn);
    #pragma unroll
    for (int i = 0; i < 4; i++) {
        float4 r;
        r.x = acc[i][0] + b4.x; r.y = acc[i][1] + b4.y;
        r.z = acc[i][2] + b4.z; r.w = acc[i][3] + b4.w;
        if (RELU) {
            r.x = fmaxf(r.x, 0.f); r.y = fmaxf(r.y, 0.f);
            r.z = fmaxf(r.z, 0.f); r.w = fmaxf(r.w, 0.f);
        }
        *reinterpret_cast<float4*>(&Cg[(size_t)(m0 + tm + i) * N + n0 + tn]) = r;
    }
}

// ---------------- final 256->1 + sigmoid ----------------
__global__ void final_kernel(const float* __restrict__ outW, const float* __restrict__ outb,
                             float* __restrict__ out, int out_size)
{
    int b = blockIdx.x, t = threadIdx.x; // 256 threads
    float p = g_x3[b * 256 + t] * outW[t];
    #pragma unroll
    for (int o = 16; o; o >>= 1) p += __shfl_xor_sync(0xffffffffu, p, o);
    __shared__ float ws[8];
    if ((t & 31) == 0) ws[t >> 5] = p;
    __syncthreads();
    if (t == 0) {
        float s = 0.f;
        #pragma unroll
        for (int i = 0; i < 8; i++) s += ws[i];
        float logit = s + outb[0];
        out[b] = 1.f / (1.f + expf(-logit));
        if (out_size >= 2 * NB) out[NB + b] = logit;
    }
}

// ---------------- launch ----------------
extern "C" void kernel_launch(void* const* d_in, const int* in_sizes, int n_in,
                              void* d_out, int out_size)
{
    const float* oh_tab = (const float*)d_in[0];
    const float* mh_tab = (const float*)d_in[1];
    const float* sp_tab = (const float*)d_in[2];
    const float* hw     = (const float*)d_in[3];
    const float* sqW = (const float*)d_in[4];  const float* sqb = (const float*)d_in[5];
    const float* skW = (const float*)d_in[6];  const float* skb = (const float*)d_in[7];
    const float* svW = (const float*)d_in[8];  const float* svb = (const float*)d_in[9];
    const float* soW = (const float*)d_in[10]; const float* sob = (const float*)d_in[11];
    const float* lqW = (const float*)d_in[12]; const float* lqb = (const float*)d_in[13];
    const float* lkW = (const float*)d_in[14]; const float* lkb = (const float*)d_in[15];
    const float* lvW = (const float*)d_in[16]; const float* lvb = (const float*)d_in[17];
    const float* loW = (const float*)d_in[18]; const float* lob = (const float*)d_in[19];
    const float* W0 = (const float*)d_in[20];  const float* b0 = (const float*)d_in[21];
    const float* W1 = (const float*)d_in[22];  const float* b1 = (const float*)d_in[23];
    const float* W2 = (const float*)d_in[24];  const float* b2 = (const float*)d_in[25];
    const float* outW = (const float*)d_in[26]; const float* outb = (const float*)d_in[27];
    const int* oh_ids = (const int*)d_in[28];
    const int* mh_ids = (const int*)d_in[29];
    const int* sp_ids = (const int*)d_in[30];
    float* out = (float*)d_out;

    // Resolve REAL device addresses of __device__ globals (host-side symbol
    // names are shadow addresses — passing them as kernel args is the round-1..3 bug).
    float *p_feats = nullptr, *p_x1 = nullptr, *p_x2 = nullptr, *p_x3 = nullptr;
    int   *p_sel = nullptr;
    cudaGetSymbolAddress((void**)&p_feats, g_feats);
    cudaGetSymbolAddress((void**)&p_x1,    g_x1);
    cudaGetSymbolAddress((void**)&p_x2,    g_x2);
    cudaGetSymbolAddress((void**)&p_x3,    g_x3);
    cudaGetSymbolAddress((void**)&p_sel,   g_sel);

    // independent preambles
    hash_rows_kernel<<<1184, 256>>>(mh_tab, hw, NFMH * NVMH);
    oh_kernel<<<NB, NFOH * 64>>>(oh_tab, oh_ids);
    sp_kernel<<<NB, NFSP * 64>>>(sp_tab, sp_ids);
    // target hashes (needs oh feats)
    th_kernel<<<256, 256>>>(hw);
    // top-K select (needs rowhash + th)
    topk_kernel<<<dim3(NB, NFMH), 256>>>(mh_ids);
    // short attention: keys = first 128 ids of each history
    attn_kernel<<<dim3(NB, NFMH), 128>>>(mh_tab, mh_ids, NS,
        sqW, sqb, skW, skb, svW, svb, soW, sob, (NFOH + NFSP) * 64);
    // long attention: keys = selected top-K ids
    attn_kernel<<<dim3(NB, NFMH), 128>>>(mh_tab, p_sel, NK,
        lqW, lqb, lkW, lkb, lvW, lvb, loW, lob, (NFOH + NFSP + NFMH) * 64);
    // MLP
    gemm_kernel<true><<<dim3(1024 / 64, NB / 64), 256>>>(p_feats, W0, b0, p_x1, NB, 1024, ND0);
    gemm_kernel<true><<<dim3(512 / 64, NB / 64), 256>>>(p_x1, W1, b1, p_x2, NB, 512, 1024);
    gemm_kernel<true><<<dim3(256 / 64, NB / 64), 256>>>(p_x2, W2, b2, p_x3, NB, 256, 512);
    final_kernel<<<NB, 256>>>(outW, outb, out, out_size);
}